// round 1
// baseline (speedup 1.0000x reference)
#include <cuda_runtime.h>

// Problem constants (fixed by setup_inputs)
#define NN 256
#define MM 2
#define TT 300
#define VV 25
#define CC 3
#define DD 256
#define KK 5
#define TOPK 64
#define ROWS (NN * MM * TT)          // 153600
#define SEL_ELEMS (NN * CC * TOPK * VV * MM)  // 2457600
#define EPSF 1e-8f

// Scratch (no allocation allowed -> __device__ globals)
__device__ float g_sums[KK * DD];
__device__ int   g_counts[KK];
__device__ float g_mean[KK * DD];
__device__ float g_inter[KK];
__device__ float g_Sb;
__device__ float g_Sw;
__device__ float g_VF[NN * TT];
__device__ int   g_idx[NN * TOPK];

// ---------------------------------------------------------------- zero scratch
__global__ void k_zero() {
    int i = blockIdx.x * blockDim.x + threadIdx.x;
    if (i < NN * TT) g_VF[i] = 0.0f;
    if (i < KK * DD) g_sums[i] = 0.0f;
    if (i < KK)      g_counts[i] = 0;
    if (i == 0)      { g_Sw = 0.0f; g_Sb = 0.0f; }
}

// ------------------------------------------------- per-class sums + counts
// 240 blocks x 256 threads; each block owns 640 rows. Thread t owns column t of
// the per-class shared accumulator -> no smem races, one atomic flush per block.
__global__ void k_segsum(const float* __restrict__ xT, const int* __restrict__ labels) {
    __shared__ float s[KK][DD];
    int tid = threadIdx.x;
#pragma unroll
    for (int k = 0; k < KK; k++) s[k][tid] = 0.0f;
    __syncthreads();

    const int R  = ROWS / 240;        // 640
    int r0 = blockIdx.x * R;
    int cnt0 = 0, cnt1 = 0, cnt2 = 0, cnt3 = 0, cnt4 = 0;
    for (int r = r0; r < r0 + R; r++) {
        int lbl = labels[r];
        s[lbl][tid] += xT[(size_t)r * DD + tid];
        if (tid == 0) {
            cnt0 += (lbl == 0); cnt1 += (lbl == 1); cnt2 += (lbl == 2);
            cnt3 += (lbl == 3); cnt4 += (lbl == 4);
        }
    }
    __syncthreads();
#pragma unroll
    for (int k = 0; k < KK; k++) atomicAdd(&g_sums[k * DD + tid], s[k][tid]);
    if (tid == 0) {
        atomicAdd(&g_counts[0], cnt0); atomicAdd(&g_counts[1], cnt1);
        atomicAdd(&g_counts[2], cnt2); atomicAdd(&g_counts[3], cnt3);
        atomicAdd(&g_counts[4], cnt4);
    }
}

// ------------------------------------ class means, overall mean, inter, Sb
__global__ void k_finalize() {
    __shared__ float red[DD];
    int tid = threadIdx.x;
    float c[KK];
    float tot = 0.0f;
#pragma unroll
    for (int k = 0; k < KK; k++) { c[k] = (float)g_counts[k]; tot += c[k]; }

    float m[KK];
    float sum_all = 0.0f;
#pragma unroll
    for (int k = 0; k < KK; k++) {
        float sk = g_sums[k * DD + tid];
        sum_all += sk;
        m[k] = sk / fmaxf(c[k], 1.0f);
        g_mean[k * DD + tid] = m[k];
    }
    float ov = sum_all / tot;   // overall mean, dim = tid

    float Sb = 0.0f;
    for (int k = 0; k < KK; k++) {
        float d = m[k] - ov;
        red[tid] = d * d;
        __syncthreads();
        for (int s = DD / 2; s > 0; s >>= 1) {
            if (tid < s) red[tid] += red[tid + s];
            __syncthreads();
        }
        if (tid == 0) { g_inter[k] = red[0]; Sb += c[k] * red[0]; }
        __syncthreads();
    }
    if (tid == 0) g_Sb = Sb;
}

// ----------------------------- intra distances, Sw, frame scores -> VF
// one warp per row; lane loads 2x float4 (row is 64 float4s)
__global__ void k_intra(const float* __restrict__ xT, const int* __restrict__ labels) {
    __shared__ float swv[8];
    int warp = threadIdx.x >> 5;
    int lane = threadIdx.x & 31;
    int row  = blockIdx.x * 8 + warp;

    int lbl = labels[row];
    const float4* rp = (const float4*)(xT + (size_t)row * DD);
    const float4* mp = (const float4*)(g_mean + lbl * DD);

    float acc = 0.0f;
    float4 a = rp[lane],      b = mp[lane];
    float d0 = a.x - b.x, d1 = a.y - b.y, d2 = a.z - b.z, d3 = a.w - b.w;
    acc += d0 * d0 + d1 * d1 + d2 * d2 + d3 * d3;
    float4 a2 = rp[lane + 32], b2 = mp[lane + 32];
    d0 = a2.x - b2.x; d1 = a2.y - b2.y; d2 = a2.z - b2.z; d3 = a2.w - b2.w;
    acc += d0 * d0 + d1 * d1 + d2 * d2 + d3 * d3;

#pragma unroll
    for (int o = 16; o > 0; o >>= 1) acc += __shfl_down_sync(0xffffffffu, acc, o);

    if (lane == 0) {
        float score = g_inter[lbl] / (acc + EPSF);
        int n = row / (MM * TT);
        int t = row % TT;
        atomicAdd(&g_VF[n * TT + t], 0.5f * score);   // mean over M=2
        swv[warp] = acc;
    }
    __syncthreads();
    if (threadIdx.x == 0) {
        float s = 0.0f;
#pragma unroll
        for (int w = 0; w < 8; w++) s += swv[w];
        atomicAdd(&g_Sw, s);
    }
}

// ---------------------------------------------------------------- scalar loss
__global__ void k_loss(float* __restrict__ out) {
    out[0] = g_Sw / (g_Sb + EPSF);
}

// ------------------------- per-row top-64 of VF[256][300], sorted ascending
// one block (256 thr) per row; bitonic sort of 512 (pad -inf), JAX tie-break:
// equal values -> lower index first.
__global__ void k_topk() {
    __shared__ float sv[512];
    __shared__ int   si[512];
    int n = blockIdx.x;
    int tid = threadIdx.x;

#pragma unroll
    for (int i = tid; i < 512; i += 256) {
        if (i < TT) { sv[i] = g_VF[n * TT + i]; si[i] = i; }
        else        { sv[i] = -__int_as_float(0x7f800000); si[i] = 1 << 30; }
    }

    // descending-by-value bitonic sort (tie: lower index first)
    for (int k = 2; k <= 512; k <<= 1) {
        for (int j = k >> 1; j > 0; j >>= 1) {
            __syncthreads();
#pragma unroll
            for (int i = tid; i < 512; i += 256) {
                int ixj = i ^ j;
                if (ixj > i) {
                    float av = sv[i], bv = sv[ixj];
                    int   ai = si[i], bi = si[ixj];
                    bool pre = (av > bv) || (av == bv && ai < bi); // a before b in target order
                    bool up  = ((i & k) == 0);
                    if (up ? !pre : pre) {
                        sv[i] = bv; sv[ixj] = av;
                        si[i] = bi; si[ixj] = ai;
                    }
                }
            }
        }
    }
    __syncthreads();

    // ascending sort of the 64 winning indices
    for (int k = 2; k <= TOPK; k <<= 1) {
        for (int j = k >> 1; j > 0; j >>= 1) {
            __syncthreads();
            if (tid < TOPK) {
                int i = tid, ixj = i ^ j;
                if (ixj > i) {
                    int a = si[i], b = si[ixj];
                    bool up = ((i & k) == 0);
                    if (up ? (a > b) : (a < b)) { si[i] = b; si[ixj] = a; }
                }
            }
        }
    }
    __syncthreads();
    if (tid < TOPK) g_idx[n * TOPK + tid] = si[tid];
}

// --------------------------------------------- gather selected frames from x
// out[n][c][j][v][m] = x[n][c][idx[n][j]][v][m]; inner 50 floats contiguous
__global__ void k_gather(const float* __restrict__ x, float* __restrict__ sel) {
    int o = blockIdx.x * blockDim.x + threadIdx.x;       // < 2457600 exactly
    int inner = o % (VV * MM);                            // 50
    int j = (o / (VV * MM)) % TOPK;
    int c = (o / (VV * MM * TOPK)) % CC;
    int n =  o / (VV * MM * TOPK * CC);
    int t = g_idx[n * TOPK + j];
    sel[o] = x[((size_t)n * CC + c) * (TT * VV * MM) + (size_t)t * (VV * MM) + inner];
}

// ============================================================================
extern "C" void kernel_launch(void* const* d_in, const int* in_sizes, int n_in,
                              void* d_out, int out_size) {
    const float* x      = (const float*)d_in[0];   // [256,3,300,25,2]
    const float* xT     = (const float*)d_in[1];   // [153600,256]
    const int*   labels = (const int*)d_in[2];     // [153600]
    (void)in_sizes; (void)n_in;

    float* out = (float*)d_out;
    int off = out_size - SEL_ELEMS;                // expected 1 (loss scalar first)
    if (off < 0) off = 0;
    float* sel = out + off;

    k_zero<<<(NN * TT + 255) / 256, 256>>>();
    k_segsum<<<240, 256>>>(xT, labels);
    k_finalize<<<1, 256>>>();
    k_intra<<<ROWS / 8, 256>>>(xT, labels);
    if (off > 0) k_loss<<<1, 1>>>(out);
    k_topk<<<NN, 256>>>();
    k_gather<<<SEL_ELEMS / 256, 256>>>(x, sel);
}

// round 2
// speedup vs baseline: 1.8407x; 1.8407x over previous
#include <cuda_runtime.h>

// Problem constants (fixed by setup_inputs)
#define NN 256
#define MM 2
#define TT 300
#define VV 25
#define CC 3
#define DD 256
#define KK 5
#define TOPK 64
#define ROWS (NN * MM * TT)          // 153600
#define SEL_ELEMS (NN * CC * TOPK * VV * MM)  // 2457600
#define EPSF 1e-8f

// Scratch (no allocation allowed -> __device__ globals)
__device__ float g_sums[KK * DD];
__device__ int   g_counts[KK];
__device__ float g_mean[KK * DD];
__device__ float g_inter[KK];
__device__ float g_Sb;
__device__ float g_Sw;
__device__ float g_VF[NN * TT];
__device__ int   g_idx[NN * TOPK];

// ---------------------------------------------------------------- zero scratch
__global__ void k_zero() {
    int i = blockIdx.x * blockDim.x + threadIdx.x;
    if (i < NN * TT) g_VF[i] = 0.0f;
    if (i < KK * DD) g_sums[i] = 0.0f;
    if (i < KK)      g_counts[i] = 0;
    if (i == 0)      { g_Sw = 0.0f; g_Sb = 0.0f; }
}

// ------------------------------------------------- per-class sums + counts
// 1200 blocks x 256 threads; each block owns 128 rows. Thread t owns column t of
// the per-class shared accumulator. Labels staged in smem; row loop unrolled for MLP.
#define SEG_R 128
__global__ void __launch_bounds__(256) k_segsum(const float* __restrict__ xT,
                                                const int* __restrict__ labels) {
    __shared__ float s[KK][DD];
    __shared__ int slbl[SEG_R];
    int tid = threadIdx.x;
#pragma unroll
    for (int k = 0; k < KK; k++) s[k][tid] = 0.0f;
    int r0 = blockIdx.x * SEG_R;
    if (tid < SEG_R) slbl[tid] = labels[r0 + tid];
    __syncthreads();

    const float* p = xT + (size_t)r0 * DD + tid;
#pragma unroll 8
    for (int r = 0; r < SEG_R; r++) {
        s[slbl[r]][tid] += p[(size_t)r * DD];
    }
    __syncthreads();
#pragma unroll
    for (int k = 0; k < KK; k++) atomicAdd(&g_sums[k * DD + tid], s[k][tid]);
    if (tid < KK) {
        int cnt = 0;
#pragma unroll 8
        for (int r = 0; r < SEG_R; r++) cnt += (slbl[r] == tid);
        atomicAdd(&g_counts[tid], cnt);
    }
}

// ------------------------------------ class means, overall mean, inter, Sb
__global__ void k_finalize() {
    __shared__ float red[DD];
    int tid = threadIdx.x;
    float c[KK];
    float tot = 0.0f;
#pragma unroll
    for (int k = 0; k < KK; k++) { c[k] = (float)g_counts[k]; tot += c[k]; }

    float m[KK];
    float sum_all = 0.0f;
#pragma unroll
    for (int k = 0; k < KK; k++) {
        float sk = g_sums[k * DD + tid];
        sum_all += sk;
        m[k] = sk / fmaxf(c[k], 1.0f);
        g_mean[k * DD + tid] = m[k];
    }
    float ov = sum_all / tot;   // overall mean, dim = tid

    float Sb = 0.0f;
    for (int k = 0; k < KK; k++) {
        float d = m[k] - ov;
        red[tid] = d * d;
        __syncthreads();
        for (int s = DD / 2; s > 0; s >>= 1) {
            if (tid < s) red[tid] += red[tid + s];
            __syncthreads();
        }
        if (tid == 0) { g_inter[k] = red[0]; Sb += c[k] * red[0]; }
        __syncthreads();
    }
    if (tid == 0) g_Sb = Sb;
}

// ----------------------------- intra distances, Sw, frame scores -> VF
// 4800 blocks x 256 thr; class means staged in smem; each warp handles 4 rows
// (independent loads batch across rows -> high MLP).
__global__ void __launch_bounds__(256) k_intra(const float* __restrict__ xT,
                                               const int* __restrict__ labels) {
    __shared__ float smean[KK * DD];
    __shared__ float sinter[KK];
    __shared__ float swv[8];
    int tid  = threadIdx.x;
    int warp = tid >> 5;
    int lane = tid & 31;

#pragma unroll
    for (int i = tid; i < KK * DD; i += 256) smean[i] = g_mean[i];
    if (tid < KK) sinter[tid] = g_inter[tid];
    __syncthreads();

    int base = blockIdx.x * 32 + warp * 4;   // 4 rows per warp

    float acc[4];
    int lbl[4];
#pragma unroll
    for (int rr = 0; rr < 4; rr++) {
        int row = base + rr;
        lbl[rr] = labels[row];
        const float4* rp = (const float4*)(xT + (size_t)row * DD);
        const float4* mp = (const float4*)(smean + lbl[rr] * DD);
        float4 a  = rp[lane],      b  = mp[lane];
        float4 a2 = rp[lane + 32], b2 = mp[lane + 32];
        float d0 = a.x - b.x,   d1 = a.y - b.y,   d2 = a.z - b.z,   d3 = a.w - b.w;
        float e0 = a2.x - b2.x, e1 = a2.y - b2.y, e2 = a2.z - b2.z, e3 = a2.w - b2.w;
        acc[rr] = d0*d0 + d1*d1 + d2*d2 + d3*d3 + e0*e0 + e1*e1 + e2*e2 + e3*e3;
    }

#pragma unroll
    for (int rr = 0; rr < 4; rr++) {
#pragma unroll
        for (int o = 16; o > 0; o >>= 1)
            acc[rr] += __shfl_down_sync(0xffffffffu, acc[rr], o);
    }

    if (lane == 0) {
        float sw4 = 0.0f;
#pragma unroll
        for (int rr = 0; rr < 4; rr++) {
            int row = base + rr;
            float score = sinter[lbl[rr]] / (acc[rr] + EPSF);
            int n = row / (MM * TT);
            int t = row % TT;
            atomicAdd(&g_VF[n * TT + t], 0.5f * score);   // mean over M=2
            sw4 += acc[rr];
        }
        swv[warp] = sw4;
    }
    __syncthreads();
    if (tid == 0) {
        float s = 0.0f;
#pragma unroll
        for (int w = 0; w < 8; w++) s += swv[w];
        atomicAdd(&g_Sw, s);
    }
}

// ---------------------------------------------------------------- scalar loss
__global__ void k_loss(float* __restrict__ out) {
    out[0] = g_Sw / (g_Sb + EPSF);
}

// ------------------------- per-row top-64 of VF[256][300], sorted ascending
// one block (256 thr) per row; bitonic sort of 512 (pad -inf), JAX tie-break:
// equal values -> lower index first.
__global__ void k_topk() {
    __shared__ float sv[512];
    __shared__ int   si[512];
    int n = blockIdx.x;
    int tid = threadIdx.x;

#pragma unroll
    for (int i = tid; i < 512; i += 256) {
        if (i < TT) { sv[i] = g_VF[n * TT + i]; si[i] = i; }
        else        { sv[i] = -__int_as_float(0x7f800000); si[i] = 1 << 30; }
    }

    // descending-by-value bitonic sort (tie: lower index first)
    for (int k = 2; k <= 512; k <<= 1) {
        for (int j = k >> 1; j > 0; j >>= 1) {
            __syncthreads();
#pragma unroll
            for (int i = tid; i < 512; i += 256) {
                int ixj = i ^ j;
                if (ixj > i) {
                    float av = sv[i], bv = sv[ixj];
                    int   ai = si[i], bi = si[ixj];
                    bool pre = (av > bv) || (av == bv && ai < bi); // a before b in target order
                    bool up  = ((i & k) == 0);
                    if (up ? !pre : pre) {
                        sv[i] = bv; sv[ixj] = av;
                        si[i] = bi; si[ixj] = ai;
                    }
                }
            }
        }
    }
    __syncthreads();

    // ascending sort of the 64 winning indices
    for (int k = 2; k <= TOPK; k <<= 1) {
        for (int j = k >> 1; j > 0; j >>= 1) {
            __syncthreads();
            if (tid < TOPK) {
                int i = tid, ixj = i ^ j;
                if (ixj > i) {
                    int a = si[i], b = si[ixj];
                    bool up = ((i & k) == 0);
                    if (up ? (a > b) : (a < b)) { si[i] = b; si[ixj] = a; }
                }
            }
        }
    }
    __syncthreads();
    if (tid < TOPK) g_idx[n * TOPK + tid] = si[tid];
}

// --------------------------------------------- gather selected frames from x
// out[n][c][j][v][m] = x[n][c][idx[n][j]][v][m]; inner 50 floats contiguous
__global__ void k_gather(const float* __restrict__ x, float* __restrict__ sel) {
    int o = blockIdx.x * blockDim.x + threadIdx.x;       // < 2457600 exactly
    int inner = o % (VV * MM);                            // 50
    int j = (o / (VV * MM)) % TOPK;
    int c = (o / (VV * MM * TOPK)) % CC;
    int n =  o / (VV * MM * TOPK * CC);
    int t = g_idx[n * TOPK + j];
    sel[o] = x[((size_t)n * CC + c) * (TT * VV * MM) + (size_t)t * (VV * MM) + inner];
}

// ============================================================================
extern "C" void kernel_launch(void* const* d_in, const int* in_sizes, int n_in,
                              void* d_out, int out_size) {
    const float* x      = (const float*)d_in[0];   // [256,3,300,25,2]
    const float* xT     = (const float*)d_in[1];   // [153600,256]
    const int*   labels = (const int*)d_in[2];     // [153600]
    (void)in_sizes; (void)n_in;

    float* out = (float*)d_out;
    int off = out_size - SEL_ELEMS;                // expected 1 (loss scalar first)
    if (off < 0) off = 0;
    float* sel = out + off;

    k_zero<<<(NN * TT + 255) / 256, 256>>>();
    k_segsum<<<ROWS / SEG_R, 256>>>(xT, labels);
    k_finalize<<<1, 256>>>();
    k_intra<<<ROWS / 32, 256>>>(xT, labels);
    if (off > 0) k_loss<<<1, 1>>>(out);
    k_topk<<<NN, 256>>>();
    k_gather<<<SEL_ELEMS / 256, 256>>>(x, sel);
}